// round 14
// baseline (speedup 1.0000x reference)
#include <cuda_runtime.h>
#include <cuda_fp16.h>
#include <math.h>
#include <stdint.h>

#define B_SZ   32
#define CH     256
#define L_SEQ  784
#define DI     512
#define DS     16
#define DCONV  4
#define DTR    16
#define MTOT   (B_SZ * L_SEQ)   // 25088
#define NCH    16
#define CL     49               // 16 * 49 = 784

#define W_IN_OFF  0
#define W_XP_OFF  262144
#define W_OUT_OFF 286720
#define WTOT      417792

// ---------------- scratch (static __device__, no allocation) ----------------
__device__ __half g_xnh[(size_t)MTOT * CH];
__device__ __half g_xnl[(size_t)MTOT * CH];
__device__ __half g_xch[(size_t)MTOT * DI];
__device__ __half g_xcl[(size_t)MTOT * DI];
__device__ __half g_yh [(size_t)MTOT * DI];
__device__ __half g_yl [(size_t)MTOT * DI];
__device__ __half g_w16[2 * (size_t)WTOT];
__device__ float g_xz  [(size_t)MTOT * 2 * DI];
__device__ float g_xdp [4][(size_t)MTOT * 48];
__device__ float g_xbuf[(size_t)B_SZ * CH * L_SEQ];
__device__ float g_hloc[(size_t)B_SZ * NCH * DS * DI];
__device__ float g_hc0 [(size_t)B_SZ * NCH * DS * DI];
__device__ float g_sdt [(size_t)B_SZ * NCH * DI];

// ============================================================================
// helpers
// ============================================================================
__device__ __forceinline__ void split16(float x, __half& h, __half& l) {
    h = __float2half_rn(x);
    l = __float2half_rn(x - __half2float(h));
}
__device__ __forceinline__ void ldsm4(uint32_t q[4], uint32_t addr) {
    asm volatile("ldmatrix.sync.aligned.m8n8.x4.shared.b16 {%0,%1,%2,%3}, [%4];"
                 : "=r"(q[0]), "=r"(q[1]), "=r"(q[2]), "=r"(q[3]) : "r"(addr));
}
__device__ __forceinline__ void mma_f16(float* c, const uint32_t a[4],
                                        uint32_t b0, uint32_t b1) {
    asm volatile("mma.sync.aligned.m16n8k16.row.col.f32.f16.f16.f32 "
                 "{%0,%1,%2,%3},{%4,%5,%6,%7},{%8,%9},{%0,%1,%2,%3};"
                 : "+f"(c[0]), "+f"(c[1]), "+f"(c[2]), "+f"(c[3])
                 : "r"(a[0]), "r"(a[1]), "r"(a[2]), "r"(a[3]), "r"(b0), "r"(b1));
}

// ---------------- weight -> fp16 (single plane), both depths ------------------
__global__ void w16_kernel(const float* __restrict__ in_w,
                           const float* __restrict__ xp_w,
                           const float* __restrict__ out_w,
                           __half* __restrict__ w16) {
    int i = blockIdx.x * 256 + threadIdx.x;
    if (i >= 2 * WTOT) return;
    int depth = i / WTOT, r = i - depth * WTOT;
    float v;
    if (r < W_XP_OFF)       v = in_w [(size_t)depth * 262144 + r];
    else if (r < W_OUT_OFF) v = xp_w [(size_t)depth * 24576  + (r - W_XP_OFF)];
    else                    v = out_w[(size_t)depth * 131072 + (r - W_OUT_OFF)];
    w16[i] = __float2half_rn(v);
}

// ============================================================================
// GEMM (R10 exact config — measured best): C = A*B^T, A pre-split fp16 hi/lo,
// B fp16, 2-term mma. BM=128, BN=NI*32, BK=16, 256 thr, 2(m)x4(n) warps,
// double buffered, 1 sync/k-tile, gridDim.z = split-K.
// ============================================================================
template<int NI, int TRANS>
__global__ void __launch_bounds__(256)
gemm_hf(const __half* __restrict__ Ah, const __half* __restrict__ Al,
        const __half* __restrict__ Bw,
        float* __restrict__ C, int M, int N, int K) {
    constexpr int RS     = 12;
    constexpr int A_U32  = 128 * RS;
    constexpr int BROWS  = NI * 32;
    constexpr int B_U32  = BROWS * RS;
    constexpr int STAGE  = 2 * A_U32 + B_U32;

    extern __shared__ uint32_t smu[];
    const uint32_t sb0 = (uint32_t)__cvta_generic_to_shared(smu);

    const int tid  = threadIdx.x;
    const int bm   = blockIdx.y * 128;
    const int bn   = blockIdx.x * BROWS;
    const int Kloc = K / gridDim.z;
    const int koff = blockIdx.z * Kloc;
    C += (size_t)blockIdx.z * M * N;

    const int warp = tid >> 5, lane = tid & 31;
    const int wm   = warp & 1, wn = warp >> 1;
    const int lm   = lane >> 3, lr = lane & 7;
    const int r    = lane >> 2, cc = lane & 3;

    const int pr = tid >> 1, ph = tid & 1;
    const int br2 = tid >> 2, bq2 = tid & 3;

    float acc[4][NI][4];
    #pragma unroll
    for (int i = 0; i < 4; i++)
        #pragma unroll
        for (int j = 0; j < NI; j++)
            #pragma unroll
            for (int v = 0; v < 4; v++) acc[i][j][v] = 0.0f;

    const int KT = Kloc >> 4;
    uint4 pAh, pAl, pB4;
    uint2 pB2;

    {
        size_t ao = (size_t)(bm + pr) * K + koff + ph * 8;
        pAh = *reinterpret_cast<const uint4*>(Ah + ao);
        pAl = *reinterpret_cast<const uint4*>(Al + ao);
        if (NI == 4) {
            int nb = min(bn + pr, N - 1);
            pB4 = *reinterpret_cast<const uint4*>(Bw + (size_t)nb * K + koff + ph * 8);
        } else {
            int nb = min(bn + br2, N - 1);
            pB2 = *reinterpret_cast<const uint2*>(Bw + (size_t)nb * K + koff + bq2 * 4);
        }
    }

    for (int kt = 0; kt < KT; kt++) {
        const int s = kt & 1;
        uint32_t* stg = smu + s * STAGE;

        *reinterpret_cast<uint4*>(stg + pr * RS + ph * 4) = pAh;
        *reinterpret_cast<uint4*>(stg + A_U32 + pr * RS + ph * 4) = pAl;
        if (NI == 4)
            *reinterpret_cast<uint4*>(stg + 2 * A_U32 + pr * RS + ph * 4) = pB4;
        else
            *reinterpret_cast<uint2*>(stg + 2 * A_U32 + br2 * RS + bq2 * 2) = pB2;

        if (kt + 1 < KT) {
            int k0 = koff + ((kt + 1) << 4);
            size_t ao = (size_t)(bm + pr) * K + k0 + ph * 8;
            pAh = *reinterpret_cast<const uint4*>(Ah + ao);
            pAl = *reinterpret_cast<const uint4*>(Al + ao);
            if (NI == 4) {
                int nb = min(bn + pr, N - 1);
                pB4 = *reinterpret_cast<const uint4*>(Bw + (size_t)nb * K + k0 + ph * 8);
            } else {
                int nb = min(bn + br2, N - 1);
                pB2 = *reinterpret_cast<const uint2*>(Bw + (size_t)nb * K + k0 + bq2 * 4);
            }
        }

        __syncthreads();

        {
            const uint32_t stb = sb0 + (uint32_t)(s * STAGE) * 4;
            uint32_t BH[NI][2];
            #pragma unroll
            for (int tt = 0; tt < NI / 2; tt++) {
                uint32_t rowb = wn * (NI * 8) + tt * 16 + (lm & 1) * 8 + lr;
                uint32_t ad = stb + (2 * A_U32) * 4 + rowb * 48 + (lm >> 1) * 16;
                uint32_t q[4];
                ldsm4(q, ad);
                BH[2*tt][0] = q[0]; BH[2*tt+1][0] = q[1];
                BH[2*tt][1] = q[2]; BH[2*tt+1][1] = q[3];
            }
            #pragma unroll
            for (int mi = 0; mi < 4; mi++) {
                uint32_t rowa = wm * 64 + mi * 16 + (lm & 1) * 8 + lr;
                uint32_t ad = stb + rowa * 48 + (lm >> 1) * 16;
                uint32_t AH[4], AL[4];
                ldsm4(AH, ad);
                ldsm4(AL, ad + A_U32 * 4);
                #pragma unroll
                for (int ni = 0; ni < NI; ni++) {
                    mma_f16(acc[mi][ni], AH, BH[ni][0], BH[ni][1]);
                    mma_f16(acc[mi][ni], AL, BH[ni][0], BH[ni][1]);
                }
            }
        }
    }

    if (!TRANS) {
        #pragma unroll
        for (int mi = 0; mi < 4; mi++) {
            int row0 = bm + wm * 64 + mi * 16 + r;
            #pragma unroll
            for (int ni = 0; ni < NI; ni++) {
                int col = bn + wn * (NI * 8) + ni * 8 + 2 * cc;
                if (col < N) {
                    *reinterpret_cast<float2*>(C + (size_t)row0 * N + col) =
                        make_float2(acc[mi][ni][0], acc[mi][ni][1]);
                    *reinterpret_cast<float2*>(C + (size_t)(row0 + 8) * N + col) =
                        make_float2(acc[mi][ni][2], acc[mi][ni][3]);
                }
            }
        }
    } else {
        float* ct = reinterpret_cast<float*>(smu);
        __syncthreads();
        #pragma unroll
        for (int half = 0; half < 2; half++) {
            if ((wn >> 1) == half) {
                #pragma unroll
                for (int mi = 0; mi < 4; mi++) {
                    int m0 = wm * 64 + mi * 16 + r;
                    #pragma unroll
                    for (int ni = 0; ni < NI; ni++) {
                        int n0 = (wn - half * 2) * (NI * 8) + ni * 8 + 2 * cc;
                        ct[(n0    ) * 132 + m0    ] = acc[mi][ni][0];
                        ct[(n0 + 1) * 132 + m0    ] = acc[mi][ni][1];
                        ct[(n0    ) * 132 + m0 + 8] = acc[mi][ni][2];
                        ct[(n0 + 1) * 132 + m0 + 8] = acc[mi][ni][3];
                    }
                }
            }
            __syncthreads();
            for (int i = tid; i < 64 * 128; i += 256) {
                int n = i >> 7, m = i & 127;
                int row = bm + m;
                int b = row / L_SEQ;
                int l = row - b * L_SEQ;
                C[((size_t)b * N + bn + half * 64 + n) * L_SEQ + l] = ct[n * 132 + m];
            }
            __syncthreads();
        }
    }
}

// ---------------- LayerNorm -> fp16 hi/lo planes, (B,C,L)->(B*L,C) ------------
__global__ void ln_kernel(const float* __restrict__ x,
                          const float* __restrict__ w,
                          const float* __restrict__ bb) {
    __shared__ float s[256][17];
    int l0 = blockIdx.x * 16;
    int b  = blockIdx.y;
    int tid = threadIdx.x;

    for (int i = tid; i < 256 * 16; i += 256) {
        int c = i >> 4, l = i & 15;
        s[c][l] = x[((size_t)b * CH + c) * L_SEQ + l0 + l];
    }
    __syncthreads();

    int l = tid >> 4, part = tid & 15;
    float a = 0.f, q = 0.f;
    #pragma unroll
    for (int j = 0; j < 16; j++) {
        float v = s[part + 16 * j][l];
        a += v;
        q = fmaf(v, v, q);
    }
    #pragma unroll
    for (int o = 1; o < 16; o <<= 1) {
        a += __shfl_xor_sync(0xffffffffu, a, o);
        q += __shfl_xor_sync(0xffffffffu, q, o);
    }
    float mu  = a * (1.0f / CH);
    float var = q * (1.0f / CH) - mu * mu;
    float inv = rsqrtf(var + 1e-5f);

    size_t base = (size_t)(b * L_SEQ + l0 + l) * CH;
    #pragma unroll
    for (int j = 0; j < 16; j++) {
        int c = part + 16 * j;
        float v = (s[c][l] - mu) * inv * w[c] + bb[c];
        __half h, lo;
        split16(v, h, lo);
        g_xnh[base + c] = h;
        g_xnl[base + c] = lo;
    }
}

// ---------------- causal conv (k=4) + SiLU -> fp16 hi/lo planes only ----------
__global__ void conv_silu_kernel(const float* __restrict__ cw,
                                 const float* __restrict__ cb) {
    int idx = blockIdx.x * 256 + threadIdx.x;
    int dq  = idx & 127;
    int d   = dq << 2;
    int blq = idx >> 7;
    int b   = blq / 196, lt = blq % 196;
    int l0  = lt * 4;
    size_t row0 = (size_t)b * L_SEQ + l0;

    float4 w0 = *reinterpret_cast<const float4*>(cw + (d + 0) * 4);
    float4 w1 = *reinterpret_cast<const float4*>(cw + (d + 1) * 4);
    float4 w2 = *reinterpret_cast<const float4*>(cw + (d + 2) * 4);
    float4 w3 = *reinterpret_cast<const float4*>(cw + (d + 3) * 4);
    const float wk[4][4] = {{w0.x, w1.x, w2.x, w3.x}, {w0.y, w1.y, w2.y, w3.y},
                            {w0.z, w1.z, w2.z, w3.z}, {w0.w, w1.w, w2.w, w3.w}};
    float4 bias4 = *reinterpret_cast<const float4*>(cb + d);

    float4 xx[7];
    #pragma unroll
    for (int k = 0; k < 7; k++) {
        int l = l0 - 3 + k;
        xx[k] = (l >= 0)
            ? *reinterpret_cast<const float4*>(g_xz + (row0 - 3 + k) * (2 * DI) + d)
            : make_float4(0.f, 0.f, 0.f, 0.f);
    }

    #pragma unroll
    for (int j = 0; j < 4; j++) {
        float4 acc = bias4;
        #pragma unroll
        for (int k = 0; k < 4; k++) {
            float4 v = xx[j + k];
            acc.x = fmaf(v.x, wk[k][0], acc.x);
            acc.y = fmaf(v.y, wk[k][1], acc.y);
            acc.z = fmaf(v.z, wk[k][2], acc.z);
            acc.w = fmaf(v.w, wk[k][3], acc.w);
        }
        float o[4] = {acc.x, acc.y, acc.z, acc.w};
        __half h[4], lo[4];
        #pragma unroll
        for (int k = 0; k < 4; k++) {
            o[k] = o[k] / (1.0f + __expf(-o[k]));
            split16(o[k], h[k], lo[k]);
        }
        size_t base = (row0 + j) * DI + d;
        *reinterpret_cast<uint2*>(g_xch + base) = *reinterpret_cast<uint2*>(h);
        *reinterpret_cast<uint2*>(g_xcl + base) = *reinterpret_cast<uint2*>(lo);
    }
}

// ============================================================================
// Chunked selective scan. p1 = R10 form (inline dt, NO g_dtv store).
// p3 recomputes dt cooperatively (per-thread weights in registers).
// ============================================================================
__device__ __forceinline__ void dA_build(float dtv, int half, bool powok,
                                         const float* a, float dA[8]) {
    if (powok) {
        float r1 = __expf(-dtv);
        float r2 = r1 * r1, r3 = r2 * r1, r4 = r2 * r2;
        dA[0] = r1; dA[1] = r2; dA[2] = r3; dA[3] = r4;
        dA[4] = r4 * r1; dA[5] = r4 * r2; dA[6] = r4 * r3; dA[7] = r4 * r4;
        if (half) {
            float r8 = r4 * r4;
            #pragma unroll
            for (int s = 0; s < 8; s++) dA[s] *= r8;
        }
    } else {
        #pragma unroll
        for (int s = 0; s < 8; s++) dA[s] = __expf(dtv * a[s]);
    }
}
__device__ __forceinline__ float xdp_sum(size_t ro) {
    return (g_xdp[0][ro] + g_xdp[1][ro]) + (g_xdp[2][ro] + g_xdp[3][ro]);
}
__device__ __forceinline__ float2 xc_load2(size_t base) {
    __half2 h2 = *reinterpret_cast<const __half2*>(g_xch + base);
    __half2 l2 = *reinterpret_cast<const __half2*>(g_xcl + base);
    float2 hf = __half22float2(h2), lf = __half22float2(l2);
    return make_float2(hf.x + lf.x, hf.y + lf.y);
}

__global__ void __launch_bounds__(128)
scan_p1(const float* __restrict__ A_log,
        const float* __restrict__ dtw, const float* __restrict__ dtb) {
    int b  = blockIdx.x, gy = blockIdx.y, ch = blockIdx.z;
    int tid = threadIdx.x;
    int dl = tid >> 1, half = tid & 1;
    int d  = gy * 64 + dl, d0 = gy * 64;

    __shared__ float sR[CL][32];   // dt_r | B
    __shared__ float sX[CL][64];

    size_t rbase = (size_t)b * L_SEQ + ch * CL;
    for (int i = tid; i < CL * 32; i += 128) {
        int st = i >> 5, j = i & 31;
        sR[st][j] = xdp_sum((rbase + st) * 48 + j);
    }
    for (int i = tid; i < CL * 32; i += 128) {
        int st = i >> 5, jp = (i & 31) * 2;
        float2 v = xc_load2((rbase + st) * DI + d0 + jp);
        sX[st][jp] = v.x; sX[st][jp + 1] = v.y;
    }
    __syncthreads();

    float w[DTR];
    #pragma unroll
    for (int i = 0; i < DTR; i++) w[i] = dtw[d * DTR + i];
    float bias = dtb[d];

    float a[8];
    bool powok = true;
    #pragma unroll
    for (int s = 0; s < 8; s++) {
        a[s] = -__expf(A_log[d * DS + half * 8 + s]);
        float kf = (float)(half * 8 + s + 1);
        powok = powok && (fabsf(-a[s] - kf) < 1e-3f * kf);
    }

    float h[8];
    #pragma unroll
    for (int s = 0; s < 8; s++) h[s] = 0.0f;
    float sumdt = 0.0f;

    for (int st = 0; st < CL; st++) {
        float s0 = 0.f, s1 = 0.f, s2 = 0.f, s3 = 0.f;
        #pragma unroll
        for (int i = 0; i < 4; i++) {
            s0 = fmaf(w[i],      sR[st][i],      s0);
            s1 = fmaf(w[4 + i],  sR[st][4 + i],  s1);
            s2 = fmaf(w[8 + i],  sR[st][8 + i],  s2);
            s3 = fmaf(w[12 + i], sR[st][12 + i], s3);
        }
        float dtl = bias + ((s0 + s1) + (s2 + s3));
        float dtv = (dtl > 20.0f) ? dtl : log1pf(__expf(dtl));
        sumdt += dtv;
        float dtx = dtv * sX[st][dl];
        float dA[8];
        dA_build(dtv, half, powok, a, dA);
        #pragma unroll
        for (int s = 0; s < 8; s++)
            h[s] = fmaf(h[s], dA[s], dtx * sR[st][16 + half * 8 + s]);
    }
    size_t hb = (((size_t)b * NCH + ch) * DS + half * 8) * DI + d;
    #pragma unroll
    for (int s = 0; s < 8; s++) g_hloc[hb + (size_t)s * DI] = h[s];
    if (half == 0) g_sdt[((size_t)b * NCH + ch) * DI + d] = sumdt;
}

__global__ void __launch_bounds__(128)
scan_p2(const float* __restrict__ A_log) {
    int idx = blockIdx.x * 128 + threadIdx.x;
    int b = idx >> 9, d = idx & (DI - 1);

    float a[16];
    bool powok = true;
    #pragma unroll
    for (int s = 0; s < 16; s++) {
        a[s] = -__expf(A_log[d * DS + s]);
        float kf = (float)(s + 1);
        powok = powok && (fabsf(-a[s] - kf) < 1e-3f * kf);
    }
    float H[16];
    #pragma unroll
    for (int s = 0; s < 16; s++) H[s] = 0.0f;

    for (int c = 0; c < NCH; c++) {
        size_t hb = (((size_t)b * NCH + c) * DS) * DI + d;
        #pragma unroll
        for (int s = 0; s < 16; s++) g_hc0[hb + (size_t)s * DI] = H[s];
        float sdt = g_sdt[((size_t)b * NCH + c) * DI + d];
        float q[16];
        if (powok) {
            float r1 = __expf(-sdt);
            float r2 = r1 * r1, r3 = r2 * r1, r4 = r2 * r2;
            q[0]=r1; q[1]=r2; q[2]=r3; q[3]=r4;
            q[4]=r4*r1; q[5]=r4*r2; q[6]=r4*r3; q[7]=r4*r4;
            float r8 = r4 * r4;
            #pragma unroll
            for (int s = 0; s < 8; s++) q[8 + s] = q[s] * r8;
        } else {
            #pragma unroll
            for (int s = 0; s < 16; s++) q[s] = __expf(sdt * a[s]);
        }
        #pragma unroll
        for (int s = 0; s < 16; s++)
            H[s] = fmaf(H[s], q[s], g_hloc[hb + (size_t)s * DI]);
    }
}

__global__ void __launch_bounds__(128)
scan_p3(const float* __restrict__ A_log, const float* __restrict__ Dp,
        const float* __restrict__ dtw, const float* __restrict__ dtb) {
    int b  = blockIdx.x, gy = blockIdx.y, ch = blockIdx.z;
    int tid = threadIdx.x;
    int dl = tid >> 1, half = tid & 1;
    int d  = gy * 64 + dl, d0 = gy * 64;

    __shared__ float sR[CL][48];    // dt_r | B | C
    __shared__ float sX[CL][64];
    __shared__ float sDT[CL][64];
    __shared__ float sZ[CL][64];

    size_t rbase = (size_t)b * L_SEQ + ch * CL;
    for (int i = tid; i < CL * 48; i += 128) {
        int st = i / 48, j = i - st * 48;
        sR[st][j] = xdp_sum((rbase + st) * 48 + j);
    }
    for (int i = tid; i < CL * 32; i += 128) {
        int st = i >> 5, jp = (i & 31) * 2;
        float2 v = xc_load2((rbase + st) * DI + d0 + jp);
        sX[st][jp] = v.x; sX[st][jp + 1] = v.y;
    }
    for (int i = tid; i < CL * 64; i += 128) {
        int st = i >> 6, j = i & 63;
        sZ[st][j] = g_xz[(rbase + st) * (2 * DI) + DI + d0 + j];
    }
    __syncthreads();

    // ---- cooperative dt recompute: per-thread dd = tid&63 is constant, so
    // the 16 dt_proj weights live in registers. Same FMA order as p1.
    {
        int dd = tid & 63;
        float wv[DTR];
        #pragma unroll
        for (int k = 0; k < DTR; k++) wv[k] = dtw[(size_t)(d0 + dd) * DTR + k];
        float bias = dtb[d0 + dd];
        for (int i = tid; i < CL * 64; i += 128) {
            int st = i >> 6;
            float s0 = 0.f, s1 = 0.f, s2 = 0.f, s3 = 0.f;
            #pragma unroll
            for (int k = 0; k < 4; k++) {
                s0 = fmaf(wv[k],      sR[st][k],      s0);
                s1 = fmaf(wv[4 + k],  sR[st][4 + k],  s1);
                s2 = fmaf(wv[8 + k],  sR[st][8 + k],  s2);
                s3 = fmaf(wv[12 + k], sR[st][12 + k], s3);
            }
            float dtl = bias + ((s0 + s1) + (s2 + s3));
            sDT[st][dd] = (dtl > 20.0f) ? dtl : log1pf(__expf(dtl));
        }
    }
    __syncthreads();

    float a[8];
    bool powok = true;
    #pragma unroll
    for (int s = 0; s < 8; s++) {
        a[s] = -__expf(A_log[d * DS + half * 8 + s]);
        float kf = (float)(half * 8 + s + 1);
        powok = powok && (fabsf(-a[s] - kf) < 1e-3f * kf);
    }
    float Dd = Dp[d];

    float h[8];
    size_t hb = (((size_t)b * NCH + ch) * DS + half * 8) * DI + d;
    #pragma unroll
    for (int s = 0; s < 8; s++) h[s] = g_hc0[hb + (size_t)s * DI];

    for (int st = 0; st < CL; st++) {
        float dtv = sDT[st][dl];
        float xv  = sX[st][dl];
        float dtx = dtv * xv;
        float dA[8];
        dA_build(dtv, half, powok, a, dA);
        float y0 = 0.f, y1 = 0.f;
        #pragma unroll
        for (int s = 0; s < 4; s++) {
            h[s] = fmaf(h[s], dA[s], dtx * sR[st][16 + half * 8 + s]);
            y0   = fmaf(h[s], sR[st][32 + half * 8 + s], y0);
        }
        #pragma unroll
        for (int s = 4; s < 8; s++) {
            h[s] = fmaf(h[s], dA[s], dtx * sR[st][16 + half * 8 + s]);
            y1   = fmaf(h[s], sR[st][32 + half * 8 + s], y1);
        }
        float yacc = y0 + y1;
        yacc += __shfl_xor_sync(0xffffffffu, yacc, 1);
        if (half == 0) {
            float zv = sZ[st][dl];
            float yf = fmaf(xv, Dd, yacc) * (zv / (1.0f + __expf(-zv)));
            __half hh, ll;
            split16(yf, hh, ll);
            g_yh[(rbase + st) * DI + d] = hh;
            g_yl[(rbase + st) * DI + d] = ll;
        }
    }
}

// ------------------------------- launcher -------------------------------------
#define SMEM_NI4 (2 * (2 * 128 * 12 + 128 * 12) * 4)   // 36864
#define SMEM_NI2 (2 * (2 * 128 * 12 + 64 * 12) * 4)    // 30720

extern "C" void kernel_launch(void* const* d_in, const int* in_sizes, int n_in,
                              void* d_out, int out_size) {
    const float* bbox   = (const float*)d_in[0];
    const float* norm_w = (const float*)d_in[1];
    const float* norm_b = (const float*)d_in[2];
    const float* in_w   = (const float*)d_in[3];
    const float* conv_w = (const float*)d_in[4];
    const float* conv_b = (const float*)d_in[5];
    const float* xp_w   = (const float*)d_in[6];
    const float* dtp_w  = (const float*)d_in[7];
    const float* dtp_b  = (const float*)d_in[8];
    const float* A_log  = (const float*)d_in[9];
    const float* Dp     = (const float*)d_in[10];
    const float* out_w  = (const float*)d_in[11];
    float* out = (float*)d_out;

    cudaFuncSetAttribute(gemm_hf<4,0>, cudaFuncAttributeMaxDynamicSharedMemorySize, SMEM_NI4);
    cudaFuncSetAttribute(gemm_hf<4,1>, cudaFuncAttributeMaxDynamicSharedMemorySize, SMEM_NI4);
    cudaFuncSetAttribute(gemm_hf<2,0>, cudaFuncAttributeMaxDynamicSharedMemorySize, SMEM_NI2);

    __half *xnh, *xnl, *xch, *xcl, *yh, *yl, *w16;
    float *xz, *xbuf, *xdp;
    cudaGetSymbolAddress((void**)&xnh, g_xnh);
    cudaGetSymbolAddress((void**)&xnl, g_xnl);
    cudaGetSymbolAddress((void**)&xch, g_xch);
    cudaGetSymbolAddress((void**)&xcl, g_xcl);
    cudaGetSymbolAddress((void**)&yh,  g_yh);
    cudaGetSymbolAddress((void**)&yl,  g_yl);
    cudaGetSymbolAddress((void**)&w16, g_w16);
    cudaGetSymbolAddress((void**)&xz,  g_xz);
    cudaGetSymbolAddress((void**)&xbuf, g_xbuf);
    cudaGetSymbolAddress((void**)&xdp,  g_xdp);

    w16_kernel<<<(2 * WTOT + 255) / 256, 256>>>(in_w, xp_w, out_w, w16);

    for (int i = 0; i < 2; i++) {
        const float* xin = (i == 0) ? bbox : xbuf;
        float* xout      = (i == 0) ? xbuf : out;
        size_t wb = (size_t)i * WTOT;

        {   // layernorm -> fp16 hi/lo planes
            dim3 g(49, 32);
            ln_kernel<<<g, 256>>>(xin, norm_w + i * CH, norm_b + i * CH);
        }
        {   // in_proj: (25088,256)x(1024,256)^T -> f32 xz
            dim3 g(1024 / 128, MTOT / 128, 1);
            gemm_hf<4,0><<<g, 256, SMEM_NI4>>>(xnh, xnl, w16 + wb + W_IN_OFF,
                                               xz, MTOT, 2 * DI, CH);
        }
        // conv + silu -> fp16 hi/lo planes only
        conv_silu_kernel<<<(MTOT / 4) * (DI / 4) / 256, 256>>>(conv_w + i * DI * DCONV,
                                                               conv_b + i * DI);
        {   // x_proj: split-K=4 -> 4 partials (reduced inside scan loaders)
            dim3 g(1, MTOT / 128, 4);
            gemm_hf<2,0><<<g, 256, SMEM_NI2>>>(xch, xcl, w16 + wb + W_XP_OFF,
                                               xdp, MTOT, 48, DI);
        }
        {   // chunked scan
            dim3 g1(B_SZ, DI / 64, NCH);
            scan_p1<<<g1, 128>>>(A_log + i * DI * DS,
                                 dtp_w + (size_t)i * DI * DTR, dtp_b + i * DI);
            scan_p2<<<(B_SZ * DI) / 128, 128>>>(A_log + i * DI * DS);
            scan_p3<<<g1, 128>>>(A_log + i * DI * DS, Dp + i * DI,
                                 dtp_w + (size_t)i * DI * DTR, dtp_b + i * DI);
        }
        {   // out_proj: (25088,512)x(256,512)^T -> (B,256,L)
            dim3 g(256 / 128, MTOT / 128, 1);
            gemm_hf<4,1><<<g, 256, SMEM_NI4>>>(yh, yl, w16 + wb + W_OUT_OFF,
                                               xout, MTOT, CH, DI);
        }
    }
}

// round 15
// speedup vs baseline: 1.0877x; 1.0877x over previous
#include <cuda_runtime.h>
#include <cuda_fp16.h>
#include <math.h>
#include <stdint.h>

#define B_SZ   32
#define CH     256
#define L_SEQ  784
#define DI     512
#define DS     16
#define DCONV  4
#define DTR    16
#define MTOT   (B_SZ * L_SEQ)   // 25088
#define NCH    16
#define CL     49               // 16 * 49 = 784

#define W_IN_OFF  0
#define W_XP_OFF  262144
#define W_OUT_OFF 286720
#define WTOT      417792

// ---------------- scratch (static __device__, no allocation) ----------------
__device__ __half g_xnh[(size_t)MTOT * CH];
__device__ __half g_xnl[(size_t)MTOT * CH];
__device__ __half g_xch[(size_t)MTOT * DI];
__device__ __half g_xcl[(size_t)MTOT * DI];
__device__ __half g_yh [(size_t)MTOT * DI];
__device__ __half g_yl [(size_t)MTOT * DI];
__device__ __half g_w16[2 * (size_t)WTOT];
__device__ float  g_xf [(size_t)MTOT * DI];   // in_proj x-half, dense f32
__device__ __half g_z16[(size_t)MTOT * DI];   // in_proj z-half, fp16
__device__ float g_xdp [4][(size_t)MTOT * 48];
__device__ float g_xbuf[(size_t)B_SZ * CH * L_SEQ];
__device__ float g_dtv [(size_t)MTOT * DI];
__device__ float g_hloc[(size_t)B_SZ * NCH * DS * DI];
__device__ float g_hc0 [(size_t)B_SZ * NCH * DS * DI];
__device__ float g_sdt [(size_t)B_SZ * NCH * DI];

// ============================================================================
// helpers
// ============================================================================
__device__ __forceinline__ void split16(float x, __half& h, __half& l) {
    h = __float2half_rn(x);
    l = __float2half_rn(x - __half2float(h));
}
__device__ __forceinline__ void ldsm4(uint32_t q[4], uint32_t addr) {
    asm volatile("ldmatrix.sync.aligned.m8n8.x4.shared.b16 {%0,%1,%2,%3}, [%4];"
                 : "=r"(q[0]), "=r"(q[1]), "=r"(q[2]), "=r"(q[3]) : "r"(addr));
}
__device__ __forceinline__ void mma_f16(float* c, const uint32_t a[4],
                                        uint32_t b0, uint32_t b1) {
    asm volatile("mma.sync.aligned.m16n8k16.row.col.f32.f16.f16.f32 "
                 "{%0,%1,%2,%3},{%4,%5,%6,%7},{%8,%9},{%0,%1,%2,%3};"
                 : "+f"(c[0]), "+f"(c[1]), "+f"(c[2]), "+f"(c[3])
                 : "r"(a[0]), "r"(a[1]), "r"(a[2]), "r"(a[3]), "r"(b0), "r"(b1));
}

// ---------------- weight -> fp16 (single plane), both depths ------------------
__global__ void w16_kernel(const float* __restrict__ in_w,
                           const float* __restrict__ xp_w,
                           const float* __restrict__ out_w,
                           __half* __restrict__ w16) {
    int i = blockIdx.x * 256 + threadIdx.x;
    if (i >= 2 * WTOT) return;
    int depth = i / WTOT, r = i - depth * WTOT;
    float v;
    if (r < W_XP_OFF)       v = in_w [(size_t)depth * 262144 + r];
    else if (r < W_OUT_OFF) v = xp_w [(size_t)depth * 24576  + (r - W_XP_OFF)];
    else                    v = out_w[(size_t)depth * 131072 + (r - W_OUT_OFF)];
    w16[i] = __float2half_rn(v);
}

// ============================================================================
// GEMM (R10 exact config): C = A*B^T, A pre-split fp16 hi/lo planes, B fp16,
// 2-term mma. BM=128, BN=NI*32, BK=16, 256 thr, 2(m)x4(n) warps, double
// buffered, 1 sync/k-tile, gridDim.z = split-K.
// ZS=1 (in_proj): x-half (bn<512) -> dense f32 C (stride 512); z-half -> fp16 Cz.
// ============================================================================
template<int NI, int TRANS, int ZS>
__global__ void __launch_bounds__(256)
gemm_hf(const __half* __restrict__ Ah, const __half* __restrict__ Al,
        const __half* __restrict__ Bw,
        float* __restrict__ C, __half* __restrict__ Cz, int M, int N, int K) {
    constexpr int RS     = 12;
    constexpr int A_U32  = 128 * RS;
    constexpr int BROWS  = NI * 32;
    constexpr int B_U32  = BROWS * RS;
    constexpr int STAGE  = 2 * A_U32 + B_U32;

    extern __shared__ uint32_t smu[];
    const uint32_t sb0 = (uint32_t)__cvta_generic_to_shared(smu);

    const int tid  = threadIdx.x;
    const int bm   = blockIdx.y * 128;
    const int bn   = blockIdx.x * BROWS;
    const int Kloc = K / gridDim.z;
    const int koff = blockIdx.z * Kloc;
    C += (size_t)blockIdx.z * M * N;

    const int warp = tid >> 5, lane = tid & 31;
    const int wm   = warp & 1, wn = warp >> 1;
    const int lm   = lane >> 3, lr = lane & 7;
    const int r    = lane >> 2, cc = lane & 3;

    const int pr = tid >> 1, ph = tid & 1;
    const int br2 = tid >> 2, bq2 = tid & 3;

    float acc[4][NI][4];
    #pragma unroll
    for (int i = 0; i < 4; i++)
        #pragma unroll
        for (int j = 0; j < NI; j++)
            #pragma unroll
            for (int v = 0; v < 4; v++) acc[i][j][v] = 0.0f;

    const int KT = Kloc >> 4;
    uint4 pAh, pAl, pB4;
    uint2 pB2;

    {
        size_t ao = (size_t)(bm + pr) * K + koff + ph * 8;
        pAh = *reinterpret_cast<const uint4*>(Ah + ao);
        pAl = *reinterpret_cast<const uint4*>(Al + ao);
        if (NI == 4) {
            int nb = min(bn + pr, N - 1);
            pB4 = *reinterpret_cast<const uint4*>(Bw + (size_t)nb * K + koff + ph * 8);
        } else {
            int nb = min(bn + br2, N - 1);
            pB2 = *reinterpret_cast<const uint2*>(Bw + (size_t)nb * K + koff + bq2 * 4);
        }
    }

    for (int kt = 0; kt < KT; kt++) {
        const int s = kt & 1;
        uint32_t* stg = smu + s * STAGE;

        *reinterpret_cast<uint4*>(stg + pr * RS + ph * 4) = pAh;
        *reinterpret_cast<uint4*>(stg + A_U32 + pr * RS + ph * 4) = pAl;
        if (NI == 4)
            *reinterpret_cast<uint4*>(stg + 2 * A_U32 + pr * RS + ph * 4) = pB4;
        else
            *reinterpret_cast<uint2*>(stg + 2 * A_U32 + br2 * RS + bq2 * 2) = pB2;

        if (kt + 1 < KT) {
            int k0 = koff + ((kt + 1) << 4);
            size_t ao = (size_t)(bm + pr) * K + k0 + ph * 8;
            pAh = *reinterpret_cast<const uint4*>(Ah + ao);
            pAl = *reinterpret_cast<const uint4*>(Al + ao);
            if (NI == 4) {
                int nb = min(bn + pr, N - 1);
                pB4 = *reinterpret_cast<const uint4*>(Bw + (size_t)nb * K + k0 + ph * 8);
            } else {
                int nb = min(bn + br2, N - 1);
                pB2 = *reinterpret_cast<const uint2*>(Bw + (size_t)nb * K + k0 + bq2 * 4);
            }
        }

        __syncthreads();

        {
            const uint32_t stb = sb0 + (uint32_t)(s * STAGE) * 4;
            uint32_t BH[NI][2];
            #pragma unroll
            for (int tt = 0; tt < NI / 2; tt++) {
                uint32_t rowb = wn * (NI * 8) + tt * 16 + (lm & 1) * 8 + lr;
                uint32_t ad = stb + (2 * A_U32) * 4 + rowb * 48 + (lm >> 1) * 16;
                uint32_t q[4];
                ldsm4(q, ad);
                BH[2*tt][0] = q[0]; BH[2*tt+1][0] = q[1];
                BH[2*tt][1] = q[2]; BH[2*tt+1][1] = q[3];
            }
            #pragma unroll
            for (int mi = 0; mi < 4; mi++) {
                uint32_t rowa = wm * 64 + mi * 16 + (lm & 1) * 8 + lr;
                uint32_t ad = stb + rowa * 48 + (lm >> 1) * 16;
                uint32_t AH[4], AL[4];
                ldsm4(AH, ad);
                ldsm4(AL, ad + A_U32 * 4);
                #pragma unroll
                for (int ni = 0; ni < NI; ni++) {
                    mma_f16(acc[mi][ni], AH, BH[ni][0], BH[ni][1]);
                    mma_f16(acc[mi][ni], AL, BH[ni][0], BH[ni][1]);
                }
            }
        }
    }

    if (!TRANS) {
        if (ZS && bn >= 512) {
            // z-half: store fp16 into Cz (row stride 512)
            #pragma unroll
            for (int mi = 0; mi < 4; mi++) {
                int row0 = bm + wm * 64 + mi * 16 + r;
                #pragma unroll
                for (int ni = 0; ni < NI; ni++) {
                    int colz = bn - 512 + wn * (NI * 8) + ni * 8 + 2 * cc;
                    __half2 v0 = __floats2half2_rn(acc[mi][ni][0], acc[mi][ni][1]);
                    __half2 v1 = __floats2half2_rn(acc[mi][ni][2], acc[mi][ni][3]);
                    *reinterpret_cast<__half2*>(Cz + (size_t)row0 * 512 + colz) = v0;
                    *reinterpret_cast<__half2*>(Cz + (size_t)(row0 + 8) * 512 + colz) = v1;
                }
            }
        } else {
            const int ldc = ZS ? 512 : N;
            #pragma unroll
            for (int mi = 0; mi < 4; mi++) {
                int row0 = bm + wm * 64 + mi * 16 + r;
                #pragma unroll
                for (int ni = 0; ni < NI; ni++) {
                    int col = bn + wn * (NI * 8) + ni * 8 + 2 * cc;
                    if (col < N) {
                        *reinterpret_cast<float2*>(C + (size_t)row0 * ldc + col) =
                            make_float2(acc[mi][ni][0], acc[mi][ni][1]);
                        *reinterpret_cast<float2*>(C + (size_t)(row0 + 8) * ldc + col) =
                            make_float2(acc[mi][ni][2], acc[mi][ni][3]);
                    }
                }
            }
        }
    } else {
        float* ct = reinterpret_cast<float*>(smu);
        __syncthreads();
        #pragma unroll
        for (int half = 0; half < 2; half++) {
            if ((wn >> 1) == half) {
                #pragma unroll
                for (int mi = 0; mi < 4; mi++) {
                    int m0 = wm * 64 + mi * 16 + r;
                    #pragma unroll
                    for (int ni = 0; ni < NI; ni++) {
                        int n0 = (wn - half * 2) * (NI * 8) + ni * 8 + 2 * cc;
                        ct[(n0    ) * 132 + m0    ] = acc[mi][ni][0];
                        ct[(n0 + 1) * 132 + m0    ] = acc[mi][ni][1];
                        ct[(n0    ) * 132 + m0 + 8] = acc[mi][ni][2];
                        ct[(n0 + 1) * 132 + m0 + 8] = acc[mi][ni][3];
                    }
                }
            }
            __syncthreads();
            for (int i = tid; i < 64 * 128; i += 256) {
                int n = i >> 7, m = i & 127;
                int row = bm + m;
                int b = row / L_SEQ;
                int l = row - b * L_SEQ;
                C[((size_t)b * N + bn + half * 64 + n) * L_SEQ + l] = ct[n * 132 + m];
            }
            __syncthreads();
        }
    }
}

// ---------------- LayerNorm -> fp16 hi/lo planes, (B,C,L)->(B*L,C) ------------
__global__ void ln_kernel(const float* __restrict__ x,
                          const float* __restrict__ w,
                          const float* __restrict__ bb) {
    __shared__ float s[256][17];
    int l0 = blockIdx.x * 16;
    int b  = blockIdx.y;
    int tid = threadIdx.x;

    for (int i = tid; i < 256 * 16; i += 256) {
        int c = i >> 4, l = i & 15;
        s[c][l] = x[((size_t)b * CH + c) * L_SEQ + l0 + l];
    }
    __syncthreads();

    int l = tid >> 4, part = tid & 15;
    float a = 0.f, q = 0.f;
    #pragma unroll
    for (int j = 0; j < 16; j++) {
        float v = s[part + 16 * j][l];
        a += v;
        q = fmaf(v, v, q);
    }
    #pragma unroll
    for (int o = 1; o < 16; o <<= 1) {
        a += __shfl_xor_sync(0xffffffffu, a, o);
        q += __shfl_xor_sync(0xffffffffu, q, o);
    }
    float mu  = a * (1.0f / CH);
    float var = q * (1.0f / CH) - mu * mu;
    float inv = rsqrtf(var + 1e-5f);

    size_t base = (size_t)(b * L_SEQ + l0 + l) * CH;
    #pragma unroll
    for (int j = 0; j < 16; j++) {
        int c = part + 16 * j;
        float v = (s[c][l] - mu) * inv * w[c] + bb[c];
        __half h, lo;
        split16(v, h, lo);
        g_xnh[base + c] = h;
        g_xnl[base + c] = lo;
    }
}

// ---------------- causal conv (k=4) + SiLU, dense x input ---------------------
__global__ void conv_silu_kernel(const float* __restrict__ cw,
                                 const float* __restrict__ cb) {
    int idx = blockIdx.x * 256 + threadIdx.x;
    int dq  = idx & 127;
    int d   = dq << 2;
    int blq = idx >> 7;
    int b   = blq / 196, lt = blq % 196;
    int l0  = lt * 4;
    size_t row0 = (size_t)b * L_SEQ + l0;

    float4 w0 = *reinterpret_cast<const float4*>(cw + (d + 0) * 4);
    float4 w1 = *reinterpret_cast<const float4*>(cw + (d + 1) * 4);
    float4 w2 = *reinterpret_cast<const float4*>(cw + (d + 2) * 4);
    float4 w3 = *reinterpret_cast<const float4*>(cw + (d + 3) * 4);
    const float wk[4][4] = {{w0.x, w1.x, w2.x, w3.x}, {w0.y, w1.y, w2.y, w3.y},
                            {w0.z, w1.z, w2.z, w3.z}, {w0.w, w1.w, w2.w, w3.w}};
    float4 bias4 = *reinterpret_cast<const float4*>(cb + d);

    float4 xx[7];
    #pragma unroll
    for (int k = 0; k < 7; k++) {
        int l = l0 - 3 + k;
        xx[k] = (l >= 0)
            ? *reinterpret_cast<const float4*>(g_xf + (row0 - 3 + k) * DI + d)
            : make_float4(0.f, 0.f, 0.f, 0.f);
    }

    #pragma unroll
    for (int j = 0; j < 4; j++) {
        float4 acc = bias4;
        #pragma unroll
        for (int k = 0; k < 4; k++) {
            float4 v = xx[j + k];
            acc.x = fmaf(v.x, wk[k][0], acc.x);
            acc.y = fmaf(v.y, wk[k][1], acc.y);
            acc.z = fmaf(v.z, wk[k][2], acc.z);
            acc.w = fmaf(v.w, wk[k][3], acc.w);
        }
        float o[4] = {acc.x, acc.y, acc.z, acc.w};
        __half h[4], lo[4];
        #pragma unroll
        for (int k = 0; k < 4; k++) {
            o[k] = o[k] / (1.0f + __expf(-o[k]));
            split16(o[k], h[k], lo[k]);
        }
        size_t base = (row0 + j) * DI + d;
        *reinterpret_cast<uint2*>(g_xch + base) = *reinterpret_cast<uint2*>(h);
        *reinterpret_cast<uint2*>(g_xcl + base) = *reinterpret_cast<uint2*>(lo);
    }
}

// ============================================================================
// Chunked selective scan (R10 exact form; p3 reads fp16 z)
// ============================================================================
__device__ __forceinline__ void dA_build(float dtv, int half, bool powok,
                                         const float* a, float dA[8]) {
    if (powok) {
        float r1 = __expf(-dtv);
        float r2 = r1 * r1, r3 = r2 * r1, r4 = r2 * r2;
        dA[0] = r1; dA[1] = r2; dA[2] = r3; dA[3] = r4;
        dA[4] = r4 * r1; dA[5] = r4 * r2; dA[6] = r4 * r3; dA[7] = r4 * r4;
        if (half) {
            float r8 = r4 * r4;
            #pragma unroll
            for (int s = 0; s < 8; s++) dA[s] *= r8;
        }
    } else {
        #pragma unroll
        for (int s = 0; s < 8; s++) dA[s] = __expf(dtv * a[s]);
    }
}
__device__ __forceinline__ float xdp_sum(size_t ro) {
    return (g_xdp[0][ro] + g_xdp[1][ro]) + (g_xdp[2][ro] + g_xdp[3][ro]);
}
__device__ __forceinline__ float2 xc_load2(size_t base) {
    __half2 h2 = *reinterpret_cast<const __half2*>(g_xch + base);
    __half2 l2 = *reinterpret_cast<const __half2*>(g_xcl + base);
    float2 hf = __half22float2(h2), lf = __half22float2(l2);
    return make_float2(hf.x + lf.x, hf.y + lf.y);
}

__global__ void __launch_bounds__(128)
scan_p1(const float* __restrict__ A_log,
        const float* __restrict__ dtw, const float* __restrict__ dtb) {
    int b  = blockIdx.x, gy = blockIdx.y, ch = blockIdx.z;
    int tid = threadIdx.x;
    int dl = tid >> 1, half = tid & 1;
    int d  = gy * 64 + dl, d0 = gy * 64;

    __shared__ float sR[CL][32];
    __shared__ float sX[CL][64];

    size_t rbase = (size_t)b * L_SEQ + ch * CL;
    for (int i = tid; i < CL * 32; i += 128) {
        int st = i >> 5, j = i & 31;
        sR[st][j] = xdp_sum((rbase + st) * 48 + j);
    }
    for (int i = tid; i < CL * 32; i += 128) {
        int st = i >> 5, jp = (i & 31) * 2;
        float2 v = xc_load2((rbase + st) * DI + d0 + jp);
        sX[st][jp] = v.x; sX[st][jp + 1] = v.y;
    }
    __syncthreads();

    float w[DTR];
    #pragma unroll
    for (int i = 0; i < DTR; i++) w[i] = dtw[d * DTR + i];
    float bias = dtb[d];

    float a[8];
    bool powok = true;
    #pragma unroll
    for (int s = 0; s < 8; s++) {
        a[s] = -__expf(A_log[d * DS + half * 8 + s]);
        float kf = (float)(half * 8 + s + 1);
        powok = powok && (fabsf(-a[s] - kf) < 1e-3f * kf);
    }

    float h[8];
    #pragma unroll
    for (int s = 0; s < 8; s++) h[s] = 0.0f;
    float sumdt = 0.0f;

    for (int st = 0; st < CL; st++) {
        float s0 = 0.f, s1 = 0.f, s2 = 0.f, s3 = 0.f;
        #pragma unroll
        for (int i = 0; i < 4; i++) {
            s0 = fmaf(w[i],      sR[st][i],      s0);
            s1 = fmaf(w[4 + i],  sR[st][4 + i],  s1);
            s2 = fmaf(w[8 + i],  sR[st][8 + i],  s2);
            s3 = fmaf(w[12 + i], sR[st][12 + i], s3);
        }
        float dtl = bias + ((s0 + s1) + (s2 + s3));
        float dtv = (dtl > 20.0f) ? dtl : log1pf(__expf(dtl));
        if (half == 0) g_dtv[(rbase + st) * DI + d] = dtv;
        sumdt += dtv;
        float dtx = dtv * sX[st][dl];
        float dA[8];
        dA_build(dtv, half, powok, a, dA);
        #pragma unroll
        for (int s = 0; s < 8; s++)
            h[s] = fmaf(h[s], dA[s], dtx * sR[st][16 + half * 8 + s]);
    }
    size_t hb = (((size_t)b * NCH + ch) * DS + half * 8) * DI + d;
    #pragma unroll
    for (int s = 0; s < 8; s++) g_hloc[hb + (size_t)s * DI] = h[s];
    if (half == 0) g_sdt[((size_t)b * NCH + ch) * DI + d] = sumdt;
}

__global__ void __launch_bounds__(128)
scan_p2(const float* __restrict__ A_log) {
    int idx = blockIdx.x * 128 + threadIdx.x;
    int b = idx >> 9, d = idx & (DI - 1);

    float a[16];
    bool powok = true;
    #pragma unroll
    for (int s = 0; s < 16; s++) {
        a[s] = -__expf(A_log[d * DS + s]);
        float kf = (float)(s + 1);
        powok = powok && (fabsf(-a[s] - kf) < 1e-3f * kf);
    }
    float H[16];
    #pragma unroll
    for (int s = 0; s < 16; s++) H[s] = 0.0f;

    for (int c = 0; c < NCH; c++) {
        size_t hb = (((size_t)b * NCH + c) * DS) * DI + d;
        #pragma unroll
        for (int s = 0; s < 16; s++) g_hc0[hb + (size_t)s * DI] = H[s];
        float sdt = g_sdt[((size_t)b * NCH + c) * DI + d];
        float q[16];
        if (powok) {
            float r1 = __expf(-sdt);
            float r2 = r1 * r1, r3 = r2 * r1, r4 = r2 * r2;
            q[0]=r1; q[1]=r2; q[2]=r3; q[3]=r4;
            q[4]=r4*r1; q[5]=r4*r2; q[6]=r4*r3; q[7]=r4*r4;
            float r8 = r4 * r4;
            #pragma unroll
            for (int s = 0; s < 8; s++) q[8 + s] = q[s] * r8;
        } else {
            #pragma unroll
            for (int s = 0; s < 16; s++) q[s] = __expf(sdt * a[s]);
        }
        #pragma unroll
        for (int s = 0; s < 16; s++)
            H[s] = fmaf(H[s], q[s], g_hloc[hb + (size_t)s * DI]);
    }
}

__global__ void __launch_bounds__(128)
scan_p3(const float* __restrict__ A_log, const float* __restrict__ Dp) {
    int b  = blockIdx.x, gy = blockIdx.y, ch = blockIdx.z;
    int tid = threadIdx.x;
    int dl = tid >> 1, half = tid & 1;
    int d  = gy * 64 + dl, d0 = gy * 64;

    __shared__ float sBC[CL][32];
    __shared__ float sX[CL][64];
    __shared__ float sDT[CL][64];
    __shared__ float sZ[CL][64];

    size_t rbase = (size_t)b * L_SEQ + ch * CL;
    for (int i = tid; i < CL * 32; i += 128) {
        int st = i >> 5, j = i & 31;
        sBC[st][j] = xdp_sum((rbase + st) * 48 + 16 + j);
    }
    for (int i = tid; i < CL * 32; i += 128) {
        int st = i >> 5, jp = (i & 31) * 2;
        float2 v = xc_load2((rbase + st) * DI + d0 + jp);
        sX[st][jp] = v.x; sX[st][jp + 1] = v.y;
        __half2 z2 = *reinterpret_cast<const __half2*>(g_z16 + (rbase + st) * DI + d0 + jp);
        float2 zf = __half22float2(z2);
        sZ[st][jp] = zf.x; sZ[st][jp + 1] = zf.y;
    }
    for (int i = tid; i < CL * 64; i += 128) {
        int st = i >> 6, j = i & 63;
        sDT[st][j] = g_dtv[(rbase + st) * DI + d0 + j];
    }
    __syncthreads();

    float a[8];
    bool powok = true;
    #pragma unroll
    for (int s = 0; s < 8; s++) {
        a[s] = -__expf(A_log[d * DS + half * 8 + s]);
        float kf = (float)(half * 8 + s + 1);
        powok = powok && (fabsf(-a[s] - kf) < 1e-3f * kf);
    }
    float Dd = Dp[d];

    float h[8];
    size_t hb = (((size_t)b * NCH + ch) * DS + half * 8) * DI + d;
    #pragma unroll
    for (int s = 0; s < 8; s++) h[s] = g_hc0[hb + (size_t)s * DI];

    for (int st = 0; st < CL; st++) {
        float dtv = sDT[st][dl];
        float xv  = sX[st][dl];
        float dtx = dtv * xv;
        float dA[8];
        dA_build(dtv, half, powok, a, dA);
        float y0 = 0.f, y1 = 0.f;
        #pragma unroll
        for (int s = 0; s < 4; s++) {
            h[s] = fmaf(h[s], dA[s], dtx * sBC[st][half * 8 + s]);
            y0   = fmaf(h[s], sBC[st][16 + half * 8 + s], y0);
        }
        #pragma unroll
        for (int s = 4; s < 8; s++) {
            h[s] = fmaf(h[s], dA[s], dtx * sBC[st][half * 8 + s]);
            y1   = fmaf(h[s], sBC[st][16 + half * 8 + s], y1);
        }
        float yacc = y0 + y1;
        yacc += __shfl_xor_sync(0xffffffffu, yacc, 1);
        if (half == 0) {
            float zv = sZ[st][dl];
            float yf = fmaf(xv, Dd, yacc) * (zv / (1.0f + __expf(-zv)));
            __half hh, ll;
            split16(yf, hh, ll);
            g_yh[(rbase + st) * DI + d] = hh;
            g_yl[(rbase + st) * DI + d] = ll;
        }
    }
}

// ------------------------------- launcher -------------------------------------
#define SMEM_NI4 (2 * (2 * 128 * 12 + 128 * 12) * 4)   // 36864
#define SMEM_NI2 (2 * (2 * 128 * 12 + 64 * 12) * 4)    // 30720

extern "C" void kernel_launch(void* const* d_in, const int* in_sizes, int n_in,
                              void* d_out, int out_size) {
    const float* bbox   = (const float*)d_in[0];
    const float* norm_w = (const float*)d_in[1];
    const float* norm_b = (const float*)d_in[2];
    const float* in_w   = (const float*)d_in[3];
    const float* conv_w = (const float*)d_in[4];
    const float* conv_b = (const float*)d_in[5];
    const float* xp_w   = (const float*)d_in[6];
    const float* dtp_w  = (const float*)d_in[7];
    const float* dtp_b  = (const float*)d_in[8];
    const float* A_log  = (const float*)d_in[9];
    const float* Dp     = (const float*)d_in[10];
    const float* out_w  = (const float*)d_in[11];
    float* out = (float*)d_out;

    cudaFuncSetAttribute(gemm_hf<4,0,1>, cudaFuncAttributeMaxDynamicSharedMemorySize, SMEM_NI4);
    cudaFuncSetAttribute(gemm_hf<4,1,0>, cudaFuncAttributeMaxDynamicSharedMemorySize, SMEM_NI4);
    cudaFuncSetAttribute(gemm_hf<2,0,0>, cudaFuncAttributeMaxDynamicSharedMemorySize, SMEM_NI2);

    __half *xnh, *xnl, *xch, *xcl, *yh, *yl, *w16, *z16;
    float *xf, *xbuf, *xdp;
    cudaGetSymbolAddress((void**)&xnh, g_xnh);
    cudaGetSymbolAddress((void**)&xnl, g_xnl);
    cudaGetSymbolAddress((void**)&xch, g_xch);
    cudaGetSymbolAddress((void**)&xcl, g_xcl);
    cudaGetSymbolAddress((void**)&yh,  g_yh);
    cudaGetSymbolAddress((void**)&yl,  g_yl);
    cudaGetSymbolAddress((void**)&w16, g_w16);
    cudaGetSymbolAddress((void**)&z16, g_z16);
    cudaGetSymbolAddress((void**)&xf,  g_xf);
    cudaGetSymbolAddress((void**)&xbuf, g_xbuf);
    cudaGetSymbolAddress((void**)&xdp,  g_xdp);

    w16_kernel<<<(2 * WTOT + 255) / 256, 256>>>(in_w, xp_w, out_w, w16);

    for (int i = 0; i < 2; i++) {
        const float* xin = (i == 0) ? bbox : xbuf;
        float* xout      = (i == 0) ? xbuf : out;
        size_t wb = (size_t)i * WTOT;

        {   // layernorm -> fp16 hi/lo planes
            dim3 g(49, 32);
            ln_kernel<<<g, 256>>>(xin, norm_w + i * CH, norm_b + i * CH);
        }
        {   // in_proj: x-half -> dense f32, z-half -> fp16
            dim3 g(1024 / 128, MTOT / 128, 1);
            gemm_hf<4,0,1><<<g, 256, SMEM_NI4>>>(xnh, xnl, w16 + wb + W_IN_OFF,
                                                 xf, z16, MTOT, 2 * DI, CH);
        }
        // conv + silu -> fp16 hi/lo planes
        conv_silu_kernel<<<(MTOT / 4) * (DI / 4) / 256, 256>>>(conv_w + i * DI * DCONV,
                                                               conv_b + i * DI);
        {   // x_proj: split-K=4 -> 4 partials (reduced inside scan loaders)
            dim3 g(1, MTOT / 128, 4);
            gemm_hf<2,0,0><<<g, 256, SMEM_NI2>>>(xch, xcl, w16 + wb + W_XP_OFF,
                                                 xdp, (__half*)nullptr, MTOT, 48, DI);
        }
        {   // chunked scan
            dim3 g1(B_SZ, DI / 64, NCH);
            scan_p1<<<g1, 128>>>(A_log + i * DI * DS,
                                 dtp_w + (size_t)i * DI * DTR, dtp_b + i * DI);
            scan_p2<<<(B_SZ * DI) / 128, 128>>>(A_log + i * DI * DS);
            scan_p3<<<g1, 128>>>(A_log + i * DI * DS, Dp + i * DI);
        }
        {   // out_proj: (25088,512)x(256,512)^T -> (B,256,L)
            dim3 g(256 / 128, MTOT / 128, 1);
            gemm_hf<4,1,0><<<g, 256, SMEM_NI4>>>(yh, yl, w16 + wb + W_OUT_OFF,
                                                 xout, (__half*)nullptr, MTOT, CH, DI);
        }
    }
}

// round 16
// speedup vs baseline: 1.1544x; 1.0614x over previous
#include <cuda_runtime.h>
#include <cuda_fp16.h>
#include <math.h>
#include <stdint.h>

#define B_SZ   32
#define CH     256
#define L_SEQ  784
#define DI     512
#define DS     16
#define DCONV  4
#define DTR    16
#define MTOT   (B_SZ * L_SEQ)   // 25088
#define NCH    16
#define CL     49               // 16 * 49 = 784

#define W_IN_OFF  0
#define W_XP_OFF  262144
#define W_OUT_OFF 286720
#define WTOT      417792

// ---------------- scratch (static __device__, no allocation) ----------------
__device__ __half g_xnh[(size_t)MTOT * CH];
__device__ __half g_xnl[(size_t)MTOT * CH];
__device__ __half g_xch[(size_t)MTOT * DI];
__device__ __half g_xcl[(size_t)MTOT * DI];
__device__ __half g_yh [(size_t)MTOT * DI];
__device__ __half g_yl [(size_t)MTOT * DI];
__device__ __half g_w16[2 * (size_t)WTOT];
__device__ float g_xz  [(size_t)MTOT * 2 * DI];
__device__ float g_xc  [(size_t)MTOT * DI];
__device__ float g_xdp [4][(size_t)MTOT * 48];
__device__ float g_xbuf[(size_t)B_SZ * CH * L_SEQ];
__device__ float g_dtv [(size_t)MTOT * DI];
__device__ float g_hloc[(size_t)B_SZ * NCH * DS * DI];
__device__ float g_hc0 [(size_t)B_SZ * NCH * DS * DI];
__device__ float g_sdt [(size_t)B_SZ * NCH * DI];

// ============================================================================
// helpers
// ============================================================================
__device__ __forceinline__ void split16(float x, __half& h, __half& l) {
    h = __float2half_rn(x);
    l = __float2half_rn(x - __half2float(h));
}
__device__ __forceinline__ void ldsm4(uint32_t q[4], uint32_t addr) {
    asm volatile("ldmatrix.sync.aligned.m8n8.x4.shared.b16 {%0,%1,%2,%3}, [%4];"
                 : "=r"(q[0]), "=r"(q[1]), "=r"(q[2]), "=r"(q[3]) : "r"(addr));
}
__device__ __forceinline__ void mma_f16(float* c, const uint32_t a[4],
                                        uint32_t b0, uint32_t b1) {
    asm volatile("mma.sync.aligned.m16n8k16.row.col.f32.f16.f16.f32 "
                 "{%0,%1,%2,%3},{%4,%5,%6,%7},{%8,%9},{%0,%1,%2,%3};"
                 : "+f"(c[0]), "+f"(c[1]), "+f"(c[2]), "+f"(c[3])
                 : "r"(a[0]), "r"(a[1]), "r"(a[2]), "r"(a[3]), "r"(b0), "r"(b1));
}

// ---------------- weight -> fp16 (single plane), both depths ------------------
__global__ void w16_kernel(const float* __restrict__ in_w,
                           const float* __restrict__ xp_w,
                           const float* __restrict__ out_w,
                           __half* __restrict__ w16) {
    int i = blockIdx.x * 256 + threadIdx.x;
    if (i >= 2 * WTOT) return;
    int depth = i / WTOT, r = i - depth * WTOT;
    float v;
    if (r < W_XP_OFF)       v = in_w [(size_t)depth * 262144 + r];
    else if (r < W_OUT_OFF) v = xp_w [(size_t)depth * 24576  + (r - W_XP_OFF)];
    else                    v = out_w[(size_t)depth * 131072 + (r - W_OUT_OFF)];
    w16[i] = __float2half_rn(v);
}

// ============================================================================
// GEMM C[M,N] = A[M,K]*B[N,K]^T ; A = pre-split fp16 hi/lo planes, B = fp16.
// 2-term mma. BM=128, BN=NI*32, BK=16, 256 thr, warps 2(m) x 4(n).
// Double buffered, 1 sync/k-tile. gridDim.z = split-K.
// ============================================================================
template<int NI, int TRANS>
__global__ void __launch_bounds__(256)
gemm_hf(const __half* __restrict__ Ah, const __half* __restrict__ Al,
        const __half* __restrict__ Bw,
        float* __restrict__ C, int M, int N, int K) {
    constexpr int RS     = 12;              // u32 per smem row (16 f16 + pad)
    constexpr int A_U32  = 128 * RS;
    constexpr int BROWS  = NI * 32;
    constexpr int B_U32  = BROWS * RS;
    constexpr int STAGE  = 2 * A_U32 + B_U32;

    extern __shared__ uint32_t smu[];
    const uint32_t sb0 = (uint32_t)__cvta_generic_to_shared(smu);

    const int tid  = threadIdx.x;
    const int bm   = blockIdx.y * 128;
    const int bn   = blockIdx.x * BROWS;
    const int Kloc = K / gridDim.z;
    const int koff = blockIdx.z * Kloc;
    C += (size_t)blockIdx.z * M * N;

    const int warp = tid >> 5, lane = tid & 31;
    const int wm   = warp & 1, wn = warp >> 1;
    const int lm   = lane >> 3, lr = lane & 7;
    const int r    = lane >> 2, cc = lane & 3;

    const int pr = tid >> 1, ph = tid & 1;
    const int br2 = tid >> 2, bq2 = tid & 3;

    float acc[4][NI][4];
    #pragma unroll
    for (int i = 0; i < 4; i++)
        #pragma unroll
        for (int j = 0; j < NI; j++)
            #pragma unroll
            for (int v = 0; v < 4; v++) acc[i][j][v] = 0.0f;

    const int KT = Kloc >> 4;
    uint4 pAh, pAl, pB4;
    uint2 pB2;

    {
        size_t ao = (size_t)(bm + pr) * K + koff + ph * 8;
        pAh = *reinterpret_cast<const uint4*>(Ah + ao);
        pAl = *reinterpret_cast<const uint4*>(Al + ao);
        if (NI == 4) {
            int nb = min(bn + pr, N - 1);
            pB4 = *reinterpret_cast<const uint4*>(Bw + (size_t)nb * K + koff + ph * 8);
        } else {
            int nb = min(bn + br2, N - 1);
            pB2 = *reinterpret_cast<const uint2*>(Bw + (size_t)nb * K + koff + bq2 * 4);
        }
    }

    for (int kt = 0; kt < KT; kt++) {
        const int s = kt & 1;
        uint32_t* stg = smu + s * STAGE;

        // ---- producer: pure STS (data already split/packed in gmem) ----
        *reinterpret_cast<uint4*>(stg + pr * RS + ph * 4) = pAh;
        *reinterpret_cast<uint4*>(stg + A_U32 + pr * RS + ph * 4) = pAl;
        if (NI == 4)
            *reinterpret_cast<uint4*>(stg + 2 * A_U32 + pr * RS + ph * 4) = pB4;
        else
            *reinterpret_cast<uint2*>(stg + 2 * A_U32 + br2 * RS + bq2 * 2) = pB2;

        // ---- prefetch next tile ----
        if (kt + 1 < KT) {
            int k0 = koff + ((kt + 1) << 4);
            size_t ao = (size_t)(bm + pr) * K + k0 + ph * 8;
            pAh = *reinterpret_cast<const uint4*>(Ah + ao);
            pAl = *reinterpret_cast<const uint4*>(Al + ao);
            if (NI == 4) {
                int nb = min(bn + pr, N - 1);
                pB4 = *reinterpret_cast<const uint4*>(Bw + (size_t)nb * K + k0 + ph * 8);
            } else {
                int nb = min(bn + br2, N - 1);
                pB2 = *reinterpret_cast<const uint2*>(Bw + (size_t)nb * K + k0 + bq2 * 4);
            }
        }

        __syncthreads();

        // ---- consumer: LDSM + 2-term fp16 mma ----
        {
            const uint32_t stb = sb0 + (uint32_t)(s * STAGE) * 4;
            uint32_t BH[NI][2];
            #pragma unroll
            for (int tt = 0; tt < NI / 2; tt++) {
                uint32_t rowb = wn * (NI * 8) + tt * 16 + (lm & 1) * 8 + lr;
                uint32_t ad = stb + (2 * A_U32) * 4 + rowb * 48 + (lm >> 1) * 16;
                uint32_t q[4];
                ldsm4(q, ad);
                BH[2*tt][0] = q[0]; BH[2*tt+1][0] = q[1];
                BH[2*tt][1] = q[2]; BH[2*tt+1][1] = q[3];
            }
            #pragma unroll
            for (int mi = 0; mi < 4; mi++) {
                uint32_t rowa = wm * 64 + mi * 16 + (lm & 1) * 8 + lr;
                uint32_t ad = stb + rowa * 48 + (lm >> 1) * 16;
                uint32_t AH[4], AL[4];
                ldsm4(AH, ad);
                ldsm4(AL, ad + A_U32 * 4);
                #pragma unroll
                for (int ni = 0; ni < NI; ni++) {
                    mma_f16(acc[mi][ni], AH, BH[ni][0], BH[ni][1]);
                    mma_f16(acc[mi][ni], AL, BH[ni][0], BH[ni][1]);
                }
            }
        }
    }

    if (!TRANS) {
        #pragma unroll
        for (int mi = 0; mi < 4; mi++) {
            int row0 = bm + wm * 64 + mi * 16 + r;
            #pragma unroll
            for (int ni = 0; ni < NI; ni++) {
                int col = bn + wn * (NI * 8) + ni * 8 + 2 * cc;
                if (col < N) {
                    *reinterpret_cast<float2*>(C + (size_t)row0 * N + col) =
                        make_float2(acc[mi][ni][0], acc[mi][ni][1]);
                    *reinterpret_cast<float2*>(C + (size_t)(row0 + 8) * N + col) =
                        make_float2(acc[mi][ni][2], acc[mi][ni][3]);
                }
            }
        }
    } else {
        float* ct = reinterpret_cast<float*>(smu);
        __syncthreads();
        #pragma unroll
        for (int half = 0; half < 2; half++) {
            if ((wn >> 1) == half) {
                #pragma unroll
                for (int mi = 0; mi < 4; mi++) {
                    int m0 = wm * 64 + mi * 16 + r;
                    #pragma unroll
                    for (int ni = 0; ni < NI; ni++) {
                        int n0 = (wn - half * 2) * (NI * 8) + ni * 8 + 2 * cc;
                        ct[(n0    ) * 132 + m0    ] = acc[mi][ni][0];
                        ct[(n0 + 1) * 132 + m0    ] = acc[mi][ni][1];
                        ct[(n0    ) * 132 + m0 + 8] = acc[mi][ni][2];
                        ct[(n0 + 1) * 132 + m0 + 8] = acc[mi][ni][3];
                    }
                }
            }
            __syncthreads();
            for (int i = tid; i < 64 * 128; i += 256) {
                int n = i >> 7, m = i & 127;
                int row = bm + m;
                int b = row / L_SEQ;
                int l = row - b * L_SEQ;
                C[((size_t)b * N + bn + half * 64 + n) * L_SEQ + l] = ct[n * 132 + m];
            }
            __syncthreads();
        }
    }
}

// ---------------- LayerNorm -> fp16 hi/lo planes, (B,C,L)->(B*L,C) ------------
__global__ void ln_kernel(const float* __restrict__ x,
                          const float* __restrict__ w,
                          const float* __restrict__ bb) {
    __shared__ float s[256][17];
    int l0 = blockIdx.x * 16;
    int b  = blockIdx.y;
    int tid = threadIdx.x;

    for (int i = tid; i < 256 * 16; i += 256) {
        int c = i >> 4, l = i & 15;
        s[c][l] = x[((size_t)b * CH + c) * L_SEQ + l0 + l];
    }
    __syncthreads();

    int l = tid >> 4, part = tid & 15;
    float a = 0.f, q = 0.f;
    #pragma unroll
    for (int j = 0; j < 16; j++) {
        float v = s[part + 16 * j][l];
        a += v;
        q = fmaf(v, v, q);
    }
    #pragma unroll
    for (int o = 1; o < 16; o <<= 1) {
        a += __shfl_xor_sync(0xffffffffu, a, o);
        q += __shfl_xor_sync(0xffffffffu, q, o);
    }
    float mu  = a * (1.0f / CH);
    float var = q * (1.0f / CH) - mu * mu;
    float inv = rsqrtf(var + 1e-5f);

    size_t base = (size_t)(b * L_SEQ + l0 + l) * CH;
    #pragma unroll
    for (int j = 0; j < 16; j++) {
        int c = part + 16 * j;
        float v = (s[c][l] - mu) * inv * w[c] + bb[c];
        __half h, lo;
        split16(v, h, lo);
        g_xnh[base + c] = h;
        g_xnl[base + c] = lo;
    }
}

// ---------------- causal conv (k=4) + SiLU -> f32 + fp16 hi/lo ----------------
__global__ void conv_silu_kernel(const float* __restrict__ cw,
                                 const float* __restrict__ cb) {
    int idx = blockIdx.x * 256 + threadIdx.x;
    int dq  = idx & 127;
    int d   = dq << 2;
    int blq = idx >> 7;
    int b   = blq / 196, lt = blq % 196;
    int l0  = lt * 4;
    size_t row0 = (size_t)b * L_SEQ + l0;

    float4 w0 = *reinterpret_cast<const float4*>(cw + (d + 0) * 4);
    float4 w1 = *reinterpret_cast<const float4*>(cw + (d + 1) * 4);
    float4 w2 = *reinterpret_cast<const float4*>(cw + (d + 2) * 4);
    float4 w3 = *reinterpret_cast<const float4*>(cw + (d + 3) * 4);
    const float wk[4][4] = {{w0.x, w1.x, w2.x, w3.x}, {w0.y, w1.y, w2.y, w3.y},
                            {w0.z, w1.z, w2.z, w3.z}, {w0.w, w1.w, w2.w, w3.w}};
    float4 bias4 = *reinterpret_cast<const float4*>(cb + d);

    float4 xx[7];
    #pragma unroll
    for (int k = 0; k < 7; k++) {
        int l = l0 - 3 + k;
        xx[k] = (l >= 0)
            ? *reinterpret_cast<const float4*>(g_xz + (row0 - 3 + k) * (2 * DI) + d)
            : make_float4(0.f, 0.f, 0.f, 0.f);
    }

    #pragma unroll
    for (int j = 0; j < 4; j++) {
        float4 acc = bias4;
        #pragma unroll
        for (int k = 0; k < 4; k++) {
            float4 v = xx[j + k];
            acc.x = fmaf(v.x, wk[k][0], acc.x);
            acc.y = fmaf(v.y, wk[k][1], acc.y);
            acc.z = fmaf(v.z, wk[k][2], acc.z);
            acc.w = fmaf(v.w, wk[k][3], acc.w);
        }
        float o[4] = {acc.x, acc.y, acc.z, acc.w};
        __half h[4], lo[4];
        #pragma unroll
        for (int k = 0; k < 4; k++) {
            o[k] = o[k] / (1.0f + __expf(-o[k]));
            split16(o[k], h[k], lo[k]);
        }
        size_t base = (row0 + j) * DI + d;
        *reinterpret_cast<float4*>(g_xc + base) = make_float4(o[0], o[1], o[2], o[3]);
        *reinterpret_cast<uint2*>(g_xch + base) = *reinterpret_cast<uint2*>(h);
        *reinterpret_cast<uint2*>(g_xcl + base) = *reinterpret_cast<uint2*>(lo);
    }
}

// ============================================================================
// Chunked selective scan (R7/R9, proven)
// ============================================================================
__device__ __forceinline__ void dA_build(float dtv, int half, bool powok,
                                         const float* a, float dA[8]) {
    if (powok) {
        float r1 = __expf(-dtv);
        float r2 = r1 * r1, r3 = r2 * r1, r4 = r2 * r2;
        dA[0] = r1; dA[1] = r2; dA[2] = r3; dA[3] = r4;
        dA[4] = r4 * r1; dA[5] = r4 * r2; dA[6] = r4 * r3; dA[7] = r4 * r4;
        if (half) {
            float r8 = r4 * r4;
            #pragma unroll
            for (int s = 0; s < 8; s++) dA[s] *= r8;
        }
    } else {
        #pragma unroll
        for (int s = 0; s < 8; s++) dA[s] = __expf(dtv * a[s]);
    }
}
__device__ __forceinline__ float xdp_sum(size_t ro) {
    return (g_xdp[0][ro] + g_xdp[1][ro]) + (g_xdp[2][ro] + g_xdp[3][ro]);
}

__global__ void __launch_bounds__(128)
scan_p1(const float* __restrict__ A_log,
        const float* __restrict__ dtw, const float* __restrict__ dtb) {
    int b  = blockIdx.x, gy = blockIdx.y, ch = blockIdx.z;
    int tid = threadIdx.x;
    int dl = tid >> 1, half = tid & 1;
    int d  = gy * 64 + dl, d0 = gy * 64;

    __shared__ float sR[CL][32];
    __shared__ float sX[CL][64];

    size_t rbase = (size_t)b * L_SEQ + ch * CL;
    for (int i = tid; i < CL * 32; i += 128) {
        int st = i >> 5, j = i & 31;
        sR[st][j] = xdp_sum((rbase + st) * 48 + j);
    }
    for (int i = tid; i < CL * 64; i += 128) {
        int st = i >> 6, j = i & 63;
        sX[st][j] = g_xc[(rbase + st) * DI + d0 + j];
    }
    __syncthreads();

    float w[DTR];
    #pragma unroll
    for (int i = 0; i < DTR; i++) w[i] = dtw[d * DTR + i];
    float bias = dtb[d];

    float a[8];
    bool powok = true;
    #pragma unroll
    for (int s = 0; s < 8; s++) {
        a[s] = -__expf(A_log[d * DS + half * 8 + s]);
        float kf = (float)(half * 8 + s + 1);
        powok = powok && (fabsf(-a[s] - kf) < 1e-3f * kf);
    }

    float h[8];
    #pragma unroll
    for (int s = 0; s < 8; s++) h[s] = 0.0f;
    float sumdt = 0.0f;

    for (int st = 0; st < CL; st++) {
        float s0 = 0.f, s1 = 0.f, s2 = 0.f, s3 = 0.f;
        #pragma unroll
        for (int i = 0; i < 4; i++) {
            s0 = fmaf(w[i],      sR[st][i],      s0);
            s1 = fmaf(w[4 + i],  sR[st][4 + i],  s1);
            s2 = fmaf(w[8 + i],  sR[st][8 + i],  s2);
            s3 = fmaf(w[12 + i], sR[st][12 + i], s3);
        }
        float dtl = bias + ((s0 + s1) + (s2 + s3));
        float dtv = (dtl > 20.0f) ? dtl : log1pf(__expf(dtl));
        if (half == 0) g_dtv[(rbase + st) * DI + d] = dtv;
        sumdt += dtv;
        float dtx = dtv * sX[st][dl];
        float dA[8];
        dA_build(dtv, half, powok, a, dA);
        #pragma unroll
        for (int s = 0; s < 8; s++)
            h[s] = fmaf(h[s], dA[s], dtx * sR[st][16 + half * 8 + s]);
    }
    size_t hb = (((size_t)b * NCH + ch) * DS + half * 8) * DI + d;
    #pragma unroll
    for (int s = 0; s < 8; s++) g_hloc[hb + (size_t)s * DI] = h[s];
    if (half == 0) g_sdt[((size_t)b * NCH + ch) * DI + d] = sumdt;
}

__global__ void __launch_bounds__(128)
scan_p2(const float* __restrict__ A_log) {
    int idx = blockIdx.x * 128 + threadIdx.x;
    int b = idx >> 9, d = idx & (DI - 1);

    float a[16];
    bool powok = true;
    #pragma unroll
    for (int s = 0; s < 16; s++) {
        a[s] = -__expf(A_log[d * DS + s]);
        float kf = (float)(s + 1);
        powok = powok && (fabsf(-a[s] - kf) < 1e-3f * kf);
    }
    float H[16];
    #pragma unroll
    for (int s = 0; s < 16; s++) H[s] = 0.0f;

    for (int c = 0; c < NCH; c++) {
        size_t hb = (((size_t)b * NCH + c) * DS) * DI + d;
        #pragma unroll
        for (int s = 0; s < 16; s++) g_hc0[hb + (size_t)s * DI] = H[s];
        float sdt = g_sdt[((size_t)b * NCH + c) * DI + d];
        float q[16];
        if (powok) {
            float r1 = __expf(-sdt);
            float r2 = r1 * r1, r3 = r2 * r1, r4 = r2 * r2;
            q[0]=r1; q[1]=r2; q[2]=r3; q[3]=r4;
            q[4]=r4*r1; q[5]=r4*r2; q[6]=r4*r3; q[7]=r4*r4;
            float r8 = r4 * r4;
            #pragma unroll
            for (int s = 0; s < 8; s++) q[8 + s] = q[s] * r8;
        } else {
            #pragma unroll
            for (int s = 0; s < 16; s++) q[s] = __expf(sdt * a[s]);
        }
        #pragma unroll
        for (int s = 0; s < 16; s++)
            H[s] = fmaf(H[s], q[s], g_hloc[hb + (size_t)s * DI]);
    }
}

__global__ void __launch_bounds__(128)
scan_p3(const float* __restrict__ A_log, const float* __restrict__ Dp) {
    int b  = blockIdx.x, gy = blockIdx.y, ch = blockIdx.z;
    int tid = threadIdx.x;
    int dl = tid >> 1, half = tid & 1;
    int d  = gy * 64 + dl, d0 = gy * 64;

    __shared__ float sBC[CL][32];
    __shared__ float sX[CL][64];
    __shared__ float sDT[CL][64];
    __shared__ float sZ[CL][64];

    size_t rbase = (size_t)b * L_SEQ + ch * CL;
    for (int i = tid; i < CL * 32; i += 128) {
        int st = i >> 5, j = i & 31;
        sBC[st][j] = xdp_sum((rbase + st) * 48 + 16 + j);
    }
    for (int i = tid; i < CL * 64; i += 128) {
        int st = i >> 6, j = i & 63;
        sX [st][j] = g_xc [(rbase + st) * DI + d0 + j];
        sDT[st][j] = g_dtv[(rbase + st) * DI + d0 + j];
        sZ [st][j] = g_xz [(rbase + st) * (2 * DI) + DI + d0 + j];
    }
    __syncthreads();

    float a[8];
    bool powok = true;
    #pragma unroll
    for (int s = 0; s < 8; s++) {
        a[s] = -__expf(A_log[d * DS + half * 8 + s]);
        float kf = (float)(half * 8 + s + 1);
        powok = powok && (fabsf(-a[s] - kf) < 1e-3f * kf);
    }
    float Dd = Dp[d];

    float h[8];
    size_t hb = (((size_t)b * NCH + ch) * DS + half * 8) * DI + d;
    #pragma unroll
    for (int s = 0; s < 8; s++) h[s] = g_hc0[hb + (size_t)s * DI];

    for (int st = 0; st < CL; st++) {
        float dtv = sDT[st][dl];
        float xv  = sX[st][dl];
        float dtx = dtv * xv;
        float dA[8];
        dA_build(dtv, half, powok, a, dA);
        float y0 = 0.f, y1 = 0.f;
        #pragma unroll
        for (int s = 0; s < 4; s++) {
            h[s] = fmaf(h[s], dA[s], dtx * sBC[st][half * 8 + s]);
            y0   = fmaf(h[s], sBC[st][16 + half * 8 + s], y0);
        }
        #pragma unroll
        for (int s = 4; s < 8; s++) {
            h[s] = fmaf(h[s], dA[s], dtx * sBC[st][half * 8 + s]);
            y1   = fmaf(h[s], sBC[st][16 + half * 8 + s], y1);
        }
        float yacc = y0 + y1;
        yacc += __shfl_xor_sync(0xffffffffu, yacc, 1);
        if (half == 0) {
            float zv = sZ[st][dl];
            float yf = fmaf(xv, Dd, yacc) * (zv / (1.0f + __expf(-zv)));
            __half hh, ll;
            split16(yf, hh, ll);
            g_yh[(rbase + st) * DI + d] = hh;
            g_yl[(rbase + st) * DI + d] = ll;
        }
    }
}

// ------------------------------- launcher -------------------------------------
#define SMEM_NI4 (2 * (2 * 128 * 12 + 128 * 12) * 4)   // 36864
#define SMEM_NI2 (2 * (2 * 128 * 12 + 64 * 12) * 4)    // 30720

extern "C" void kernel_launch(void* const* d_in, const int* in_sizes, int n_in,
                              void* d_out, int out_size) {
    const float* bbox   = (const float*)d_in[0];
    const float* norm_w = (const float*)d_in[1];
    const float* norm_b = (const float*)d_in[2];
    const float* in_w   = (const float*)d_in[3];
    const float* conv_w = (const float*)d_in[4];
    const float* conv_b = (const float*)d_in[5];
    const float* xp_w   = (const float*)d_in[6];
    const float* dtp_w  = (const float*)d_in[7];
    const float* dtp_b  = (const float*)d_in[8];
    const float* A_log  = (const float*)d_in[9];
    const float* Dp     = (const float*)d_in[10];
    const float* out_w  = (const float*)d_in[11];
    float* out = (float*)d_out;

    cudaFuncSetAttribute(gemm_hf<4,0>, cudaFuncAttributeMaxDynamicSharedMemorySize, SMEM_NI4);
    cudaFuncSetAttribute(gemm_hf<4,1>, cudaFuncAttributeMaxDynamicSharedMemorySize, SMEM_NI4);
    cudaFuncSetAttribute(gemm_hf<2,0>, cudaFuncAttributeMaxDynamicSharedMemorySize, SMEM_NI2);

    __half *xnh, *xnl, *xch, *xcl, *yh, *yl, *w16;
    float *xz, *xbuf, *xdp;
    cudaGetSymbolAddress((void**)&xnh, g_xnh);
    cudaGetSymbolAddress((void**)&xnl, g_xnl);
    cudaGetSymbolAddress((void**)&xch, g_xch);
    cudaGetSymbolAddress((void**)&xcl, g_xcl);
    cudaGetSymbolAddress((void**)&yh,  g_yh);
    cudaGetSymbolAddress((void**)&yl,  g_yl);
    cudaGetSymbolAddress((void**)&w16, g_w16);
    cudaGetSymbolAddress((void**)&xz,  g_xz);
    cudaGetSymbolAddress((void**)&xbuf, g_xbuf);
    cudaGetSymbolAddress((void**)&xdp,  g_xdp);

    // convert all weights to fp16 once per launch (both depths)
    w16_kernel<<<(2 * WTOT + 255) / 256, 256>>>(in_w, xp_w, out_w, w16);

    for (int i = 0; i < 2; i++) {
        const float* xin = (i == 0) ? bbox : xbuf;
        float* xout      = (i == 0) ? xbuf : out;
        size_t wb = (size_t)i * WTOT;

        {   // layernorm -> fp16 hi/lo planes
            dim3 g(49, 32);
            ln_kernel<<<g, 256>>>(xin, norm_w + i * CH, norm_b + i * CH);
        }
        {   // in_proj: (25088,256)x(1024,256)^T -> f32 xz
            dim3 g(1024 / 128, MTOT / 128, 1);
            gemm_hf<4,0><<<g, 256, SMEM_NI4>>>(xnh, xnl, w16 + wb + W_IN_OFF,
                                               xz, MTOT, 2 * DI, CH);
        }
        // conv + silu -> f32 + fp16 planes
        conv_silu_kernel<<<(MTOT / 4) * (DI / 4) / 256, 256>>>(conv_w + i * DI * DCONV,
                                                               conv_b + i * DI);
        {   // x_proj: split-K=4 -> 4 partials (reduced inside scan loaders)
            dim3 g(1, MTOT / 128, 4);
            gemm_hf<2,0><<<g, 256, SMEM_NI2>>>(xch, xcl, w16 + wb + W_XP_OFF,
                                               xdp, MTOT, 48, DI);
        }
        {   // chunked scan
            dim3 g1(B_SZ, DI / 64, NCH);
            scan_p1<<<g1, 128>>>(A_log + i * DI * DS,
                                 dtp_w + (size_t)i * DI * DTR, dtp_b + i * DI);
            scan_p2<<<(B_SZ * DI) / 128, 128>>>(A_log + i * DI * DS);
            scan_p3<<<g1, 128>>>(A_log + i * DI * DS, Dp + i * DI);
        }
        {   // out_proj: (25088,512)x(256,512)^T -> (B,256,L)
            dim3 g(256 / 128, MTOT / 128, 1);
            gemm_hf<4,1><<<g, 256, SMEM_NI4>>>(yh, yl, w16 + wb + W_OUT_OFF,
                                               xout, MTOT, CH, DI);
        }
    }
}